// round 14
// baseline (speedup 1.0000x reference)
#include <cuda_runtime.h>
#include <cuda_fp16.h>
#include <cstdint>

// Attention_41480794145302 — mma.sync fp16 m16n8k16 (f32 accum), frag-packed
// smem.  R13 projections + attention with cross-iteration MMA pipelining:
// MMA2(it-1) interleaved with MMA1(it) so exp is off the tensor critical path.
// x:[B,512,L]  w_qkv:[1536,512]  w_out:[512,512]  b_out:[512]  out:[B,512,L]

namespace {
constexpr int Bn  = 4;
constexpr int DIM = 512;
constexpr int Ln  = 2048;
constexpr int Hn  = 8;
constexpr int DH  = 64;
constexpr int HID = 512;
constexpr float SCALE = 0.125f;   // 64^-0.5
}

// scratch (allocation-free rule: __device__ globals)
__device__ float g_q[Bn * Hn * Ln * DH];  // [b,h,l,c]
__device__ float g_k[Bn * Hn * Ln * DH];  // [b,h,l,c]
__device__ float g_v[Bn * Hn * Ln * DH];  // [b,h,l,c]
__device__ float g_o[Bn * HID * Ln];      // [b, h*64+c, l]

__device__ __forceinline__ uint32_t f2h2(float lo, float hi) {
    __half2 h = __floats2half2_rn(lo, hi);
    return *(uint32_t*)&h;
}

// D += A(16x16,row) * B(16x8,col)  fp16, f32 accum
__device__ __forceinline__ void mma16(float* c, const uint32_t* a, const uint32_t* b) {
    asm volatile(
        "mma.sync.aligned.m16n8k16.row.col.f32.f16.f16.f32 "
        "{%0,%1,%2,%3}, {%4,%5,%6,%7}, {%8,%9}, {%0,%1,%2,%3};"
        : "+f"(c[0]), "+f"(c[1]), "+f"(c[2]), "+f"(c[3])
        : "r"(a[0]), "r"(a[1]), "r"(a[2]), "r"(a[3]), "r"(b[0]), "r"(b[1]));
}

// ---------------------------------------------------------------------------
// fp16 fragment-packed smem layouts (validated R12 scheme; words = half2).
// A region = 16(M)x16(K) tile: 128 words + pad -> 132.  One LDS.128 per frag.
// B region = 16(K)x8(N) tile: 64 words + pad -> 66.  One LDS.64 per frag.
// ---------------------------------------------------------------------------
__device__ __forceinline__ int ha_word(int region, int rr, int kk) {
    const int lane = (((rr & 7) * 4 + ((kk >> 1) & 3)) ^ ((rr >> 1) & 3));
    return region * 132 + lane * 4 + (rr >> 3) + 2 * (kk >> 3);
}
__device__ __forceinline__ void a_frag16(uint32_t* a, const uint32_t* base,
                                         int region, int g, int tig) {
    const uint4 f = *(const uint4*)&base[region * 132 + (((g * 4 + tig) ^ ((g >> 1) & 3)) * 4)];
    a[0] = f.x; a[1] = f.y; a[2] = f.z; a[3] = f.w;
}
__device__ __forceinline__ int hb_word(int region, int kk, int nn) {
    const int m = (region ^ (region >> 3)) & 3;
    return region * 66 + (((nn * 4 + ((kk >> 1) & 3)) ^ m) * 2) + (kk >> 3);
}
__device__ __forceinline__ void b_frag16(uint32_t* b, const uint32_t* base,
                                         int region, int g, int tig) {
    const int m = (region ^ (region >> 3)) & 3;
    const uint2 f = *(const uint2*)&base[region * 66 + (((g * 4 + tig) ^ m) * 2)];
    b[0] = f.x; b[1] = f.y;
}

// ---------------------------------------------------------------------------
// Kernel 1: QKV projection.  C[1536,2048] = w_qkv[1536,512] @ x_b[512,2048]
// Block tile 128(M) x 128(N), K-chunk 64, 8 warps, warp tile 32x64.
// ---------------------------------------------------------------------------
__global__ __launch_bounds__(256, 2) void qkv_mma(const float* __restrict__ x,
                                                  const float* __restrict__ w) {
    __shared__ uint32_t WsP[32 * 132];   // A-pack: 8 mtiles x 4 ktiles
    __shared__ uint32_t XsP[64 * 66];    // B-pack: 4 ktiles x 16 ntiles

    const int t    = threadIdx.x;
    const int w8   = t >> 5;
    const int lane = t & 31;
    const int g    = lane >> 2;
    const int tig  = lane & 3;
    const int wm   = w8 & 3;
    const int wn   = w8 >> 2;
    const int ltile = blockIdx.x * 128;
    const int bm    = blockIdx.y;
    const int b     = blockIdx.z;

    const float* xb = x + (size_t)b * DIM * Ln;

    float acc[16][4] = {};

    for (int kc = 0; kc < DIM; kc += 64) {
        __syncthreads();
        // W tile 128x64 -> A-pack
        #pragma unroll
        for (int jj = 0; jj < 8; jj++) {
            const int pos = t + 256 * jj;
            const int r   = pos >> 4;
            const int c4  = (pos & 15) * 4;
            const float4 v = *(const float4*)&w[(size_t)(bm * 128 + r) * DIM + kc + c4];
            const int region = (r >> 4) * 4 + (c4 >> 4);
            const int rr = r & 15;
            const int kk = c4 & 15;
            WsP[ha_word(region, rr, kk)]     = f2h2(v.x, v.y);
            WsP[ha_word(region, rr, kk + 2)] = f2h2(v.z, v.w);
        }
        // X tile 64x128 -> B-pack
        #pragma unroll
        for (int jj = 0; jj < 4; jj++) {
            const int p  = (t >> 4) + (jj & 1) * 16;
            const int l0 = (t & 15) * 4 + (jj >> 1) * 64;
            const float4 A = *(const float4*)&xb[(size_t)(kc + 2 * p) * Ln + ltile + l0];
            const float4 B = *(const float4*)&xb[(size_t)(kc + 2 * p + 1) * Ln + ltile + l0];
            const int kk = (2 * p) & 15;
            const int kt2 = (2 * p) >> 4;
            XsP[hb_word(kt2 * 16 + ((l0 + 0) >> 3), kk, (l0 + 0) & 7)] = f2h2(A.x, B.x);
            XsP[hb_word(kt2 * 16 + ((l0 + 1) >> 3), kk, (l0 + 1) & 7)] = f2h2(A.y, B.y);
            XsP[hb_word(kt2 * 16 + ((l0 + 2) >> 3), kk, (l0 + 2) & 7)] = f2h2(A.z, B.z);
            XsP[hb_word(kt2 * 16 + ((l0 + 3) >> 3), kk, (l0 + 3) & 7)] = f2h2(A.w, B.w);
        }
        __syncthreads();

        #pragma unroll
        for (int ks = 0; ks < 4; ks++) {
            uint32_t a[2][4];
            a_frag16(a[0], WsP, (wm * 2 + 0) * 4 + ks, g, tig);
            a_frag16(a[1], WsP, (wm * 2 + 1) * 4 + ks, g, tig);
            #pragma unroll
            for (int nt = 0; nt < 8; nt++) {
                uint32_t bf[2];
                b_frag16(bf, XsP, ks * 16 + wn * 8 + nt, g, tig);
                mma16(acc[nt], a[0], bf);
                mma16(acc[8 + nt], a[1], bf);
            }
        }
    }

    // epilogue: scatter into heads layout (f32)
    #pragma unroll
    for (int mt = 0; mt < 2; mt++) {
        #pragma unroll
        for (int nt = 0; nt < 8; nt++) {
            #pragma unroll
            for (int reg = 0; reg < 4; reg++) {
                const int m = bm * 128 + wm * 32 + mt * 16 + g + ((reg >= 2) ? 8 : 0);
                const int l = ltile + wn * 64 + nt * 8 + tig * 2 + (reg & 1);
                const int tile = m >> 6;
                const int sec  = tile >> 3;
                const int h    = tile & 7;
                const int c    = m & 63;
                float val = acc[mt * 8 + nt][reg];
                if (sec == 0) val *= SCALE;
                float* dst = (sec == 0) ? g_q : ((sec == 1) ? g_k : g_v);
                dst[((size_t)(b * Hn + h) * Ln + l) * DH + c] = val;
            }
        }
    }
}

// ---------------------------------------------------------------------------
// Kernel 2: flash attention, fp16, cross-iteration MMA pipelining.
// Block = 128 q-rows; KV tiles of 64; 8 warps, warp tile 16 rows x 64 keys.
// Per iteration: STS tile(it); sync1; [MMA1(it) + MMA2(it-1) interleaved];
// exp(it)->pa; sync2 (protects buf[(it-1)&1] before it+1 overwrites it).
// ---------------------------------------------------------------------------
namespace {
constexpr int NQP = 32 * 132;   // Q A-pack
constexpr int NKP = 32 * 66;    // K B-pack
constexpr int NVP = 32 * 66;    // V B-pack
constexpr int OFF_QP = 0;
constexpr int OFF_KP = OFF_QP + NQP;
constexpr int OFF_VP = OFF_KP + 2 * NKP;
constexpr int ATTN_SMEM = (OFF_VP + 2 * NVP) * 4;   // 50688 B
}

__global__ __launch_bounds__(256, 2) void attn_mma() {
    extern __shared__ uint32_t sm[];
    uint32_t* QP = sm + OFF_QP;

    const int t    = threadIdx.x;
    const int w8   = t >> 5;
    const int lane = t & 31;
    const int g    = lane >> 2;
    const int tig  = lane & 3;
    const int wm   = w8;              // 16-row slice per warp
    const int bh   = blockIdx.y;
    const int lq0  = blockIdx.x * 128;

    const float* qb = g_q + (size_t)bh * Ln * DH;
    const float* kb = g_k + (size_t)bh * Ln * DH;
    const float* vb = g_v + (size_t)bh * Ln * DH;

    // Q tile 128x64 -> A-pack
    #pragma unroll
    for (int jj = 0; jj < 8; jj++) {
        const int pos = t + 256 * jj;
        const int r   = pos >> 4;
        const int c4  = (pos & 15) * 4;
        const float4 v = *(const float4*)&qb[(size_t)(lq0 + r) * DH + c4];
        const int region = (r >> 4) * 4 + (c4 >> 4);
        const int rr = r & 15;
        const int kk = c4 & 15;
        QP[ha_word(region, rr, kk)]     = f2h2(v.x, v.y);
        QP[ha_word(region, rr, kk + 2)] = f2h2(v.z, v.w);
    }
    __syncthreads();

    // hoist Q fragments (loop-invariant A operand): 4 k16 steps
    uint32_t qf[4][4];
    #pragma unroll
    for (int ks = 0; ks < 4; ks++)
        a_frag16(qf[ks], QP, wm * 4 + ks, g, tig);

    // per-thread KV load coords
    const int key  = t >> 2;           // 0..63  (K rows)
    const int c16  = (t & 3) * 16;     // K c-offset
    const int vp   = t >> 4;           // V key-pair base 0..15
    const int vc4  = (t & 15) * 4;     // V c-offset

    float oacc[8][4] = {};            // [nt2][reg]
    float ps_tot[2] = {0.0f, 0.0f};   // row sums (rows g, g+8)
    uint32_t pa[4][4];                // P fragments of the PREVIOUS iteration

    for (int it = 0; it < Ln / 64; it++) {
        uint32_t* KP  = sm + OFF_KP + (it & 1) * NKP;
        uint32_t* VP  = sm + OFF_VP + (it & 1) * NVP;
        uint32_t* VPp = sm + OFF_VP + ((it & 1) ^ 1) * NVP;   // prev V tile
        const int kt = it * 64;

        // load + convert + pack KV tile it
        #pragma unroll
        for (int u = 0; u < 4; u++) {
            const int c4 = c16 + u * 4;
            const float4 kv = *(const float4*)&kb[(size_t)(kt + key) * DH + c4];
            const int region = (c4 >> 4) * 8 + (key >> 3);
            const int kk = c4 & 15;
            const int nn = key & 7;
            KP[hb_word(region, kk, nn)]     = f2h2(kv.x, kv.y);
            KP[hb_word(region, kk + 2, nn)] = f2h2(kv.z, kv.w);
        }
        #pragma unroll
        for (int jj = 0; jj < 2; jj++) {
            const int p = vp + jj * 16;
            const float4 A = *(const float4*)&vb[(size_t)(kt + 2 * p) * DH + vc4];
            const float4 B = *(const float4*)&vb[(size_t)(kt + 2 * p + 1) * DH + vc4];
            const int kk = (2 * p) & 15;
            const int kt2 = (2 * p) >> 4;
            VP[hb_word(kt2 * 8 + ((vc4 + 0) >> 3), kk, (vc4 + 0) & 7)] = f2h2(A.x, B.x);
            VP[hb_word(kt2 * 8 + ((vc4 + 1) >> 3), kk, (vc4 + 1) & 7)] = f2h2(A.y, B.y);
            VP[hb_word(kt2 * 8 + ((vc4 + 2) >> 3), kk, (vc4 + 2) & 7)] = f2h2(A.z, B.z);
            VP[hb_word(kt2 * 8 + ((vc4 + 3) >> 3), kk, (vc4 + 3) & 7)] = f2h2(A.w, B.w);
        }
        __syncthreads();   // sync1: tile it visible everywhere

        // MMA phase: MMA1(it) + MMA2(it-1) interleaved (continuous tensor run)
        float s[8][4] = {};
        if (it > 0) {
            #pragma unroll
            for (int ks = 0; ks < 4; ks++) {
                #pragma unroll
                for (int nt = 0; nt < 8; nt++) {
                    uint32_t bf[2], bv[2];
                    b_frag16(bf, KP, ks * 8 + nt, g, tig);
                    mma16(s[nt], qf[ks], bf);
                    b_frag16(bv, VPp, ks * 8 + nt, g, tig);
                    mma16(oacc[nt], pa[ks], bv);
                }
            }
        } else {
            #pragma unroll
            for (int ks = 0; ks < 4; ks++) {
                #pragma unroll
                for (int nt = 0; nt < 8; nt++) {
                    uint32_t bf[2];
                    b_frag16(bf, KP, ks * 8 + nt, g, tig);
                    mma16(s[nt], qf[ks], bf);
                }
            }
        }

        // exp + row sums -> pa (P fragments for NEXT iteration's MMA2)
        #pragma unroll
        for (int nt = 0; nt < 8; nt++) {
            const float e0 = __expf(s[nt][0]);
            const float e1 = __expf(s[nt][1]);
            const float e2 = __expf(s[nt][2]);
            const float e3 = __expf(s[nt][3]);
            ps_tot[0] += e0 + e1;
            ps_tot[1] += e2 + e3;
            pa[nt >> 1][(nt & 1) * 2 + 0] = f2h2(e0, e1);
            pa[nt >> 1][(nt & 1) * 2 + 1] = f2h2(e2, e3);
        }
        __syncthreads();   // sync2: all reads of buf[(it-1)&1] complete
    }

    // drain: MMA2 for the final tile
    {
        uint32_t* VPl = sm + OFF_VP + ((Ln / 64 - 1) & 1) * NVP;
        #pragma unroll
        for (int ks2 = 0; ks2 < 4; ks2++) {
            #pragma unroll
            for (int nt2 = 0; nt2 < 8; nt2++) {
                uint32_t bv[2];
                b_frag16(bv, VPl, ks2 * 8 + nt2, g, tig);
                mma16(oacc[nt2], pa[ks2], bv);
            }
        }
    }

    // row-sum completion over the 4 tig lanes
    float ls[2];
    #pragma unroll
    for (int hf = 0; hf < 2; hf++) {
        float v = ps_tot[hf];
        v += __shfl_xor_sync(0xffffffffu, v, 1);
        v += __shfl_xor_sync(0xffffffffu, v, 2);
        ls[hf] = 1.0f / v;
    }

    const int b = bh >> 3, h = bh & 7;
    #pragma unroll
    for (int nt2 = 0; nt2 < 8; nt2++) {
        #pragma unroll
        for (int reg = 0; reg < 4; reg++) {
            const int hf  = reg >> 1;
            const int row = wm * 16 + g + hf * 8;
            const int c   = nt2 * 8 + tig * 2 + (reg & 1);
            g_o[((size_t)b * HID + h * 64 + c) * Ln + lq0 + row] =
                oacc[nt2][reg] * ls[hf];
        }
    }
}

// ---------------------------------------------------------------------------
// Kernel 3: output projection.  out[b] = w_out[512,512] @ g_o_b[512,2048]+bias
// K-chunk 64, same structure as qkv_mma.
// ---------------------------------------------------------------------------
__global__ __launch_bounds__(256, 2) void outp_mma(const float* __restrict__ w,
                                                   const float* __restrict__ bias,
                                                   float* __restrict__ out) {
    __shared__ uint32_t WsP[32 * 132];
    __shared__ uint32_t XsP[64 * 66];

    const int t    = threadIdx.x;
    const int w8   = t >> 5;
    const int lane = t & 31;
    const int g    = lane >> 2;
    const int tig  = lane & 3;
    const int wm   = w8 & 3;
    const int wn   = w8 >> 2;
    const int ltile = blockIdx.x * 128;
    const int bm    = blockIdx.y;
    const int b     = blockIdx.z;

    const float* xb = g_o + (size_t)b * HID * Ln;

    float acc[16][4] = {};

    for (int kc = 0; kc < HID; kc += 64) {
        __syncthreads();
        #pragma unroll
        for (int jj = 0; jj < 8; jj++) {
            const int pos = t + 256 * jj;
            const int r   = pos >> 4;
            const int c4  = (pos & 15) * 4;
            const float4 v = *(const float4*)&w[(size_t)(bm * 128 + r) * HID + kc + c4];
            const int region = (r >> 4) * 4 + (c4 >> 4);
            const int rr = r & 15;
            const int kk = c4 & 15;
            WsP[ha_word(region, rr, kk)]     = f2h2(v.x, v.y);
            WsP[ha_word(region, rr, kk + 2)] = f2h2(v.z, v.w);
        }
        #pragma unroll
        for (int jj = 0; jj < 4; jj++) {
            const int p  = (t >> 4) + (jj & 1) * 16;
            const int l0 = (t & 15) * 4 + (jj >> 1) * 64;
            const float4 A = *(const float4*)&xb[(size_t)(kc + 2 * p) * Ln + ltile + l0];
            const float4 B = *(const float4*)&xb[(size_t)(kc + 2 * p + 1) * Ln + ltile + l0];
            const int kk = (2 * p) & 15;
            const int kt2 = (2 * p) >> 4;
            XsP[hb_word(kt2 * 16 + ((l0 + 0) >> 3), kk, (l0 + 0) & 7)] = f2h2(A.x, B.x);
            XsP[hb_word(kt2 * 16 + ((l0 + 1) >> 3), kk, (l0 + 1) & 7)] = f2h2(A.y, B.y);
            XsP[hb_word(kt2 * 16 + ((l0 + 2) >> 3), kk, (l0 + 2) & 7)] = f2h2(A.z, B.z);
            XsP[hb_word(kt2 * 16 + ((l0 + 3) >> 3), kk, (l0 + 3) & 7)] = f2h2(A.w, B.w);
        }
        __syncthreads();

        #pragma unroll
        for (int ks = 0; ks < 4; ks++) {
            uint32_t a[2][4];
            a_frag16(a[0], WsP, (wm * 2 + 0) * 4 + ks, g, tig);
            a_frag16(a[1], WsP, (wm * 2 + 1) * 4 + ks, g, tig);
            #pragma unroll
            for (int nt = 0; nt < 8; nt++) {
                uint32_t bf[2];
                b_frag16(bf, XsP, ks * 16 + wn * 8 + nt, g, tig);
                mma16(acc[nt], a[0], bf);
                mma16(acc[8 + nt], a[1], bf);
            }
        }
    }

    #pragma unroll
    for (int mt = 0; mt < 2; mt++) {
        #pragma unroll
        for (int nt = 0; nt < 8; nt++) {
            #pragma unroll
            for (int reg = 0; reg < 4; reg++) {
                const int m = bm * 128 + wm * 32 + mt * 16 + g + ((reg >= 2) ? 8 : 0);
                const int l = ltile + wn * 64 + nt * 8 + tig * 2 + (reg & 1);
                out[((size_t)b * DIM + m) * Ln + l] = acc[mt * 8 + nt][reg] + bias[m];
            }
        }
    }
}

// ---------------------------------------------------------------------------
extern "C" void kernel_launch(void* const* d_in, const int* in_sizes, int n_in,
                              void* d_out, int out_size) {
    const float* x     = (const float*)d_in[0];
    const float* w_qkv = (const float*)d_in[1];
    const float* w_out = (const float*)d_in[2];
    const float* b_out = (const float*)d_in[3];
    float* out = (float*)d_out;

    cudaFuncSetAttribute(attn_mma, cudaFuncAttributeMaxDynamicSharedMemorySize, ATTN_SMEM);

    qkv_mma<<<dim3(Ln / 128, (3 * HID) / 128, Bn), 256>>>(x, w_qkv);
    attn_mma<<<dim3(Ln / 128, Bn * Hn), 256, ATTN_SMEM>>>();
    outp_mma<<<dim3(Ln / 128, HID / 128, Bn), 256>>>(w_out, b_out, out);
}

// round 15
// speedup vs baseline: 1.2929x; 1.2929x over previous
#include <cuda_runtime.h>
#include <cuda_fp16.h>
#include <cstdint>

// Attention_41480794145302 — mma.sync fp16 m16n8k16 (f32 accum), frag-packed
// smem.  R12/R13 structure; intermediates g_q/g_k/g_v/g_o stored as fp16 in
// global (halves LDG bytes, deletes all converts in attn/outp pack loops).
// x:[B,512,L]  w_qkv:[1536,512]  w_out:[512,512]  b_out:[512]  out:[B,512,L]

namespace {
constexpr int Bn  = 4;
constexpr int DIM = 512;
constexpr int Ln  = 2048;
constexpr int Hn  = 8;
constexpr int DH  = 64;
constexpr int HID = 512;
constexpr float SCALE = 0.125f;   // 64^-0.5
}

// scratch (allocation-free rule: __device__ globals) — fp16 intermediates
__device__ __half g_q[Bn * Hn * Ln * DH];  // [b,h,l,c]
__device__ __half g_k[Bn * Hn * Ln * DH];  // [b,h,l,c]
__device__ __half g_v[Bn * Hn * Ln * DH];  // [b,h,l,c]
__device__ __half g_o[Bn * HID * Ln];      // [b, h*64+c, l]

__device__ __forceinline__ uint32_t f2h2(float lo, float hi) {
    __half2 h = __floats2half2_rn(lo, hi);
    return *(uint32_t*)&h;
}

// D += A(16x16,row) * B(16x8,col)  fp16, f32 accum
__device__ __forceinline__ void mma16(float* c, const uint32_t* a, const uint32_t* b) {
    asm volatile(
        "mma.sync.aligned.m16n8k16.row.col.f32.f16.f16.f32 "
        "{%0,%1,%2,%3}, {%4,%5,%6,%7}, {%8,%9}, {%0,%1,%2,%3};"
        : "+f"(c[0]), "+f"(c[1]), "+f"(c[2]), "+f"(c[3])
        : "r"(a[0]), "r"(a[1]), "r"(a[2]), "r"(a[3]), "r"(b[0]), "r"(b[1]));
}

// ---------------------------------------------------------------------------
// fp16 fragment-packed smem layouts (validated R12 scheme; words = half2).
// ---------------------------------------------------------------------------
__device__ __forceinline__ int ha_word(int region, int rr, int kk) {
    const int lane = (((rr & 7) * 4 + ((kk >> 1) & 3)) ^ ((rr >> 1) & 3));
    return region * 132 + lane * 4 + (rr >> 3) + 2 * (kk >> 3);
}
__device__ __forceinline__ void a_frag16(uint32_t* a, const uint32_t* base,
                                         int region, int g, int tig) {
    const uint4 f = *(const uint4*)&base[region * 132 + (((g * 4 + tig) ^ ((g >> 1) & 3)) * 4)];
    a[0] = f.x; a[1] = f.y; a[2] = f.z; a[3] = f.w;
}
__device__ __forceinline__ int hb_word(int region, int kk, int nn) {
    const int m = (region ^ (region >> 3)) & 3;
    return region * 66 + (((nn * 4 + ((kk >> 1) & 3)) ^ m) * 2) + (kk >> 3);
}
__device__ __forceinline__ void b_frag16(uint32_t* b, const uint32_t* base,
                                         int region, int g, int tig) {
    const int m = (region ^ (region >> 3)) & 3;
    const uint2 f = *(const uint2*)&base[region * 66 + (((g * 4 + tig) ^ m) * 2)];
    b[0] = f.x; b[1] = f.y;
}

// ---------------------------------------------------------------------------
// Kernel 1: QKV projection.  C[1536,2048] = w_qkv[1536,512] @ x_b[512,2048]
// Block tile 128(M) x 128(N), K-chunk 64, 8 warps, warp tile 32x64.
// Epilogue writes fp16 intermediates.
// ---------------------------------------------------------------------------
__global__ __launch_bounds__(256, 2) void qkv_mma(const float* __restrict__ x,
                                                  const float* __restrict__ w) {
    __shared__ uint32_t WsP[32 * 132];   // A-pack: 8 mtiles x 4 ktiles
    __shared__ uint32_t XsP[64 * 66];    // B-pack: 4 ktiles x 16 ntiles

    const int t    = threadIdx.x;
    const int w8   = t >> 5;
    const int lane = t & 31;
    const int g    = lane >> 2;
    const int tig  = lane & 3;
    const int wm   = w8 & 3;
    const int wn   = w8 >> 2;
    const int ltile = blockIdx.x * 128;
    const int bm    = blockIdx.y;
    const int b     = blockIdx.z;

    const float* xb = x + (size_t)b * DIM * Ln;

    float acc[16][4] = {};

    for (int kc = 0; kc < DIM; kc += 64) {
        __syncthreads();
        // W tile 128x64 (f32) -> A-pack
        #pragma unroll
        for (int jj = 0; jj < 8; jj++) {
            const int pos = t + 256 * jj;
            const int r   = pos >> 4;
            const int c4  = (pos & 15) * 4;
            const float4 v = *(const float4*)&w[(size_t)(bm * 128 + r) * DIM + kc + c4];
            const int region = (r >> 4) * 4 + (c4 >> 4);
            const int rr = r & 15;
            const int kk = c4 & 15;
            WsP[ha_word(region, rr, kk)]     = f2h2(v.x, v.y);
            WsP[ha_word(region, rr, kk + 2)] = f2h2(v.z, v.w);
        }
        // X tile 64x128 (f32) -> B-pack
        #pragma unroll
        for (int jj = 0; jj < 4; jj++) {
            const int p  = (t >> 4) + (jj & 1) * 16;
            const int l0 = (t & 15) * 4 + (jj >> 1) * 64;
            const float4 A = *(const float4*)&xb[(size_t)(kc + 2 * p) * Ln + ltile + l0];
            const float4 B = *(const float4*)&xb[(size_t)(kc + 2 * p + 1) * Ln + ltile + l0];
            const int kk = (2 * p) & 15;
            const int kt2 = (2 * p) >> 4;
            XsP[hb_word(kt2 * 16 + ((l0 + 0) >> 3), kk, (l0 + 0) & 7)] = f2h2(A.x, B.x);
            XsP[hb_word(kt2 * 16 + ((l0 + 1) >> 3), kk, (l0 + 1) & 7)] = f2h2(A.y, B.y);
            XsP[hb_word(kt2 * 16 + ((l0 + 2) >> 3), kk, (l0 + 2) & 7)] = f2h2(A.z, B.z);
            XsP[hb_word(kt2 * 16 + ((l0 + 3) >> 3), kk, (l0 + 3) & 7)] = f2h2(A.w, B.w);
        }
        __syncthreads();

        #pragma unroll
        for (int ks = 0; ks < 4; ks++) {
            uint32_t a[2][4];
            a_frag16(a[0], WsP, (wm * 2 + 0) * 4 + ks, g, tig);
            a_frag16(a[1], WsP, (wm * 2 + 1) * 4 + ks, g, tig);
            #pragma unroll
            for (int nt = 0; nt < 8; nt++) {
                uint32_t bf[2];
                b_frag16(bf, XsP, ks * 16 + wn * 8 + nt, g, tig);
                mma16(acc[nt], a[0], bf);
                mma16(acc[8 + nt], a[1], bf);
            }
        }
    }

    // epilogue: scatter fp16 into heads layout
    #pragma unroll
    for (int mt = 0; mt < 2; mt++) {
        #pragma unroll
        for (int nt = 0; nt < 8; nt++) {
            #pragma unroll
            for (int reg = 0; reg < 4; reg++) {
                const int m = bm * 128 + wm * 32 + mt * 16 + g + ((reg >= 2) ? 8 : 0);
                const int l = ltile + wn * 64 + nt * 8 + tig * 2 + (reg & 1);
                const int tile = m >> 6;
                const int sec  = tile >> 3;
                const int h    = tile & 7;
                const int c    = m & 63;
                float val = acc[mt * 8 + nt][reg];
                if (sec == 0) val *= SCALE;
                __half* dst = (sec == 0) ? g_q : ((sec == 1) ? g_k : g_v);
                dst[((size_t)(b * Hn + h) * Ln + l) * DH + c] = __float2half_rn(val);
            }
        }
    }
}

// ---------------------------------------------------------------------------
// Kernel 2: flash attention, fp16 end-to-end loads.  Block = 128 q-rows;
// KV tiles of 64; 8 warps, warp tile 16 rows x 64 keys.  Q A-frags hoisted;
// P straight from S accumulators.  Double-buffered KV, 1 sync per iteration.
// Packs are pure word rearrangement (no cvt): K/Q pairs come pre-paired
// along c; V pairs across rows via 2 PRMT per word.
// ---------------------------------------------------------------------------
namespace {
constexpr int NQP = 32 * 132;   // Q A-pack
constexpr int NKP = 32 * 66;    // K B-pack
constexpr int NVP = 32 * 66;    // V B-pack
constexpr int OFF_QP = 0;
constexpr int OFF_KP = OFF_QP + NQP;
constexpr int OFF_VP = OFF_KP + 2 * NKP;
constexpr int ATTN_SMEM = (OFF_VP + 2 * NVP) * 4;   // 50688 B
}

__global__ __launch_bounds__(256, 2) void attn_mma() {
    extern __shared__ uint32_t sm[];
    uint32_t* QP = sm + OFF_QP;

    const int t    = threadIdx.x;
    const int w8   = t >> 5;
    const int lane = t & 31;
    const int g    = lane >> 2;
    const int tig  = lane & 3;
    const int wm   = w8;              // 16-row slice per warp
    const int bh   = blockIdx.y;
    const int lq0  = blockIdx.x * 128;

    const __half* qb = g_q + (size_t)bh * Ln * DH;
    const __half* kb = g_k + (size_t)bh * Ln * DH;
    const __half* vb = g_v + (size_t)bh * Ln * DH;

    // Q tile 128x64 halves -> A-pack (LDG.128 -> 4 STS.32, no cvt)
    #pragma unroll
    for (int jj = 0; jj < 4; jj++) {
        const int pos = t + 256 * jj;
        const int r   = pos >> 3;          // 0..127
        const int c8  = (pos & 7) * 8;     // 0..56
        const uint4 U = *(const uint4*)&qb[(size_t)(lq0 + r) * DH + c8];
        const int region = (r >> 4) * 4 + (c8 >> 4);
        const int rr = r & 15;
        const int kk = c8 & 15;            // 0 or 8
        QP[ha_word(region, rr, kk + 0)] = U.x;
        QP[ha_word(region, rr, kk + 2)] = U.y;
        QP[ha_word(region, rr, kk + 4)] = U.z;
        QP[ha_word(region, rr, kk + 6)] = U.w;
    }
    __syncthreads();

    // hoist Q fragments (loop-invariant A operand): 4 k16 steps
    uint32_t qf[4][4];
    #pragma unroll
    for (int ks = 0; ks < 4; ks++)
        a_frag16(qf[ks], QP, wm * 4 + ks, g, tig);

    float oacc[8][4] = {};            // [nt2][reg]
    float ps_tot[2] = {0.0f, 0.0f};   // row sums (rows g, g+8)

    for (int it = 0; it < Ln / 64; it++) {
        uint32_t* KP = sm + OFF_KP + (it & 1) * NKP;
        uint32_t* VP = sm + OFF_VP + (it & 1) * NVP;
        const int kt = it * 64;

        // K tile 64x64 halves -> B-pack (2 tasks/thread, no cvt)
        #pragma unroll
        for (int jj = 0; jj < 2; jj++) {
            const int pos = t + 256 * jj;
            const int key = pos >> 3;          // 0..63
            const int c8  = (pos & 7) * 8;
            const uint4 U = *(const uint4*)&kb[(size_t)(kt + key) * DH + c8];
            const int region = (c8 >> 4) * 8 + (key >> 3);
            const int kk = c8 & 15;
            const int nn = key & 7;
            KP[hb_word(region, kk + 0, nn)] = U.x;
            KP[hb_word(region, kk + 2, nn)] = U.y;
            KP[hb_word(region, kk + 4, nn)] = U.z;
            KP[hb_word(region, kk + 6, nn)] = U.w;
        }
        // V tile: pairs across adjacent keys (1 task/thread: 2 rows x 8 c)
        {
            const int pair = t >> 3;           // 0..31
            const int c8   = (t & 7) * 8;
            const uint4 A = *(const uint4*)&vb[(size_t)(kt + 2 * pair) * DH + c8];
            const uint4 B = *(const uint4*)&vb[(size_t)(kt + 2 * pair + 1) * DH + c8];
            const int kk  = (2 * pair) & 15;
            const int region = ((2 * pair) >> 4) * 8 + (c8 >> 3);
            VP[hb_word(region, kk, 0)] = __byte_perm(A.x, B.x, 0x5410);
            VP[hb_word(region, kk, 1)] = __byte_perm(A.x, B.x, 0x7632);
            VP[hb_word(region, kk, 2)] = __byte_perm(A.y, B.y, 0x5410);
            VP[hb_word(region, kk, 3)] = __byte_perm(A.y, B.y, 0x7632);
            VP[hb_word(region, kk, 4)] = __byte_perm(A.z, B.z, 0x5410);
            VP[hb_word(region, kk, 5)] = __byte_perm(A.z, B.z, 0x7632);
            VP[hb_word(region, kk, 6)] = __byte_perm(A.w, B.w, 0x5410);
            VP[hb_word(region, kk, 7)] = __byte_perm(A.w, B.w, 0x7632);
        }
        __syncthreads();   // this buffer visible; other buffer's readers done

        // MMA1: S[16,64] = Q . K^T  (contraction c=64, 4 k16 steps)
        float s[8][4] = {};
        #pragma unroll
        for (int ks = 0; ks < 4; ks++) {
            #pragma unroll
            for (int nt = 0; nt < 8; nt++) {
                uint32_t bf[2];
                b_frag16(bf, KP, ks * 8 + nt, g, tig);
                mma16(s[nt], qf[ks], bf);
            }
        }

        // exp + row sums + build fp16 A-frags for MMA2 directly from accums
        uint32_t pa[4][4];
        #pragma unroll
        for (int nt = 0; nt < 8; nt++) {
            const float e0 = __expf(s[nt][0]);
            const float e1 = __expf(s[nt][1]);
            const float e2 = __expf(s[nt][2]);
            const float e3 = __expf(s[nt][3]);
            ps_tot[0] += e0 + e1;
            ps_tot[1] += e2 + e3;
            pa[nt >> 1][(nt & 1) * 2 + 0] = f2h2(e0, e1);
            pa[nt >> 1][(nt & 1) * 2 + 1] = f2h2(e2, e3);
        }

        // MMA2: O[16,64] += P . V  (contraction key=64, 4 k16 steps)
        #pragma unroll
        for (int ks2 = 0; ks2 < 4; ks2++) {
            #pragma unroll
            for (int nt2 = 0; nt2 < 8; nt2++) {
                uint32_t bf[2];
                b_frag16(bf, VP, ks2 * 8 + nt2, g, tig);
                mma16(oacc[nt2], pa[ks2], bf);
            }
        }
    }

    // row-sum completion over the 4 tig lanes
    float ls[2];
    #pragma unroll
    for (int hf = 0; hf < 2; hf++) {
        float v = ps_tot[hf];
        v += __shfl_xor_sync(0xffffffffu, v, 1);
        v += __shfl_xor_sync(0xffffffffu, v, 2);
        ls[hf] = 1.0f / v;
    }

    const int b = bh >> 3, h = bh & 7;
    #pragma unroll
    for (int nt2 = 0; nt2 < 8; nt2++) {
        #pragma unroll
        for (int reg = 0; reg < 4; reg++) {
            const int hf  = reg >> 1;
            const int row = wm * 16 + g + hf * 8;
            const int c   = nt2 * 8 + tig * 2 + (reg & 1);
            g_o[((size_t)b * HID + h * 64 + c) * Ln + lq0 + row] =
                __float2half_rn(oacc[nt2][reg] * ls[hf]);
        }
    }
}

// ---------------------------------------------------------------------------
// Kernel 3: output projection.  out[b] = w_out[512,512] @ g_o_b[512,2048]+bias
// K-chunk 64; X (g_o) is fp16 [c][l]: pairs along c via PRMT (like V).
// ---------------------------------------------------------------------------
__global__ __launch_bounds__(256, 2) void outp_mma(const float* __restrict__ w,
                                                   const float* __restrict__ bias,
                                                   float* __restrict__ out) {
    __shared__ uint32_t WsP[32 * 132];
    __shared__ uint32_t XsP[64 * 66];

    const int t    = threadIdx.x;
    const int w8   = t >> 5;
    const int lane = t & 31;
    const int g    = lane >> 2;
    const int tig  = lane & 3;
    const int wm   = w8 & 3;
    const int wn   = w8 >> 2;
    const int ltile = blockIdx.x * 128;
    const int bm    = blockIdx.y;
    const int b     = blockIdx.z;

    const __half* xb = g_o + (size_t)b * HID * Ln;

    float acc[16][4] = {};

    for (int kc = 0; kc < HID; kc += 64) {
        __syncthreads();
        // W tile 128x64 (f32) -> A-pack
        #pragma unroll
        for (int jj = 0; jj < 8; jj++) {
            const int pos = t + 256 * jj;
            const int r   = pos >> 4;
            const int c4  = (pos & 15) * 4;
            const float4 v = *(const float4*)&w[(size_t)(bm * 128 + r) * HID + kc + c4];
            const int region = (r >> 4) * 4 + (c4 >> 4);
            const int rr = r & 15;
            const int kk = c4 & 15;
            WsP[ha_word(region, rr, kk)]     = f2h2(v.x, v.y);
            WsP[ha_word(region, rr, kk + 2)] = f2h2(v.z, v.w);
        }
        // X tile 64x128 halves -> B-pack (2 tasks/thread; PRMT pairing)
        #pragma unroll
        for (int jj = 0; jj < 2; jj++) {
            const int pos  = t + 256 * jj;
            const int pair = pos >> 4;          // 0..31 (c-pairs)
            const int l8   = (pos & 15) * 8;
            const uint4 A = *(const uint4*)&xb[(size_t)(kc + 2 * pair) * Ln + ltile + l8];
            const uint4 B = *(const uint4*)&xb[(size_t)(kc + 2 * pair + 1) * Ln + ltile + l8];
            const int kk  = (2 * pair) & 15;
            const int region = ((2 * pair) >> 4) * 16 + (l8 >> 3);
            XsP[hb_word(region, kk, 0)] = __byte_perm(A.x, B.x, 0x5410);
            XsP[hb_word(region, kk, 1)] = __byte_perm(A.x, B.x, 0x7632);
            XsP[hb_word(region, kk, 2)] = __byte_perm(A.y, B.y, 0x5410);
            XsP[hb_word(region, kk, 3)] = __byte_perm(A.y, B.y, 0x7632);
            XsP[hb_word(region, kk, 4)] = __byte_perm(A.z, B.z, 0x5410);
            XsP[hb_word(region, kk, 5)] = __byte_perm(A.z, B.z, 0x7632);
            XsP[hb_word(region, kk, 6)] = __byte_perm(A.w, B.w, 0x5410);
            XsP[hb_word(region, kk, 7)] = __byte_perm(A.w, B.w, 0x7632);
        }
        __syncthreads();

        #pragma unroll
        for (int ks = 0; ks < 4; ks++) {
            uint32_t a[2][4];
            a_frag16(a[0], WsP, (wm * 2 + 0) * 4 + ks, g, tig);
            a_frag16(a[1], WsP, (wm * 2 + 1) * 4 + ks, g, tig);
            #pragma unroll
            for (int nt = 0; nt < 8; nt++) {
                uint32_t bf[2];
                b_frag16(bf, XsP, ks * 16 + wn * 8 + nt, g, tig);
                mma16(acc[nt], a[0], bf);
                mma16(acc[8 + nt], a[1], bf);
            }
        }
    }

    #pragma unroll
    for (int mt = 0; mt < 2; mt++) {
        #pragma unroll
        for (int nt = 0; nt < 8; nt++) {
            #pragma unroll
            for (int reg = 0; reg < 4; reg++) {
                const int m = bm * 128 + wm * 32 + mt * 16 + g + ((reg >= 2) ? 8 : 0);
                const int l = ltile + wn * 64 + nt * 8 + tig * 2 + (reg & 1);
                out[((size_t)b * DIM + m) * Ln + l] = acc[mt * 8 + nt][reg] + bias[m];
            }
        }
    }
}

// ---------------------------------------------------------------------------
extern "C" void kernel_launch(void* const* d_in, const int* in_sizes, int n_in,
                              void* d_out, int out_size) {
    const float* x     = (const float*)d_in[0];
    const float* w_qkv = (const float*)d_in[1];
    const float* w_out = (const float*)d_in[2];
    const float* b_out = (const float*)d_in[3];
    float* out = (float*)d_out;

    cudaFuncSetAttribute(attn_mma, cudaFuncAttributeMaxDynamicSharedMemorySize, ATTN_SMEM);

    qkv_mma<<<dim3(Ln / 128, (3 * HID) / 128, Bn), 256>>>(x, w_qkv);
    attn_mma<<<dim3(Ln / 128, Bn * Hn), 256, ATTN_SMEM>>>();
    outp_mma<<<dim3(Ln / 128, HID / 128, Bn), 256>>>(w_out, b_out, out);
}